// round 1
// baseline (speedup 1.0000x reference)
#include <cuda_runtime.h>

typedef unsigned long long u64;

#define NPOS (4096*128)
#define TILE 128
#define NTILES (NPOS/TILE)      // 4096
#define THREADS 256
#define NBLOCKS 1024

// ---- packed fp32x2 helpers (sm_103a) ----
static __device__ __forceinline__ u64 fma2(u64 a, u64 b, u64 c) {
    u64 d;
    asm("fma.rn.f32x2 %0, %1, %2, %3;" : "=l"(d) : "l"(a), "l"(b), "l"(c));
    return d;
}
union F2 { u64 u; float2 f; };
static __device__ __forceinline__ u64 dup2(float x) { F2 t; t.f.x = x; t.f.y = x; return t.u; }

struct __align__(16) Smem {
    float  X[3][TILE];       // input tile
    float  Val[TILE];        // validity mask
    float4 W1[64];           // folded layer1: a0,a1,a2,c
    float  C2[64];
    float  C3[128];
    float  Inv2[64];
    float  Inv3[128];
    float  W2D[64][128];     // [k][2*o] duplicated pairs (folded)
    float  W3D[64][256];     // [k][2*o] duplicated pairs (folded)
    float  Y1[64][TILE];
    float  Y2[64][TILE];
};

extern "C" __global__ void __launch_bounds__(THREADS, 1)
pn_fused_kernel(const float* __restrict__ pc,  const float* __restrict__ valid,
                const float* __restrict__ W1,  const float* __restrict__ b1,
                const float* __restrict__ g1,  const float* __restrict__ be1,
                const float* __restrict__ m1,  const float* __restrict__ v1,
                const float* __restrict__ W2,  const float* __restrict__ b2,
                const float* __restrict__ g2,  const float* __restrict__ be2,
                const float* __restrict__ m2,  const float* __restrict__ v2,
                const float* __restrict__ W3,  const float* __restrict__ b3,
                const float* __restrict__ g3,  const float* __restrict__ be3,
                const float* __restrict__ m3,  const float* __restrict__ v3,
                float* __restrict__ out)
{
    extern __shared__ char smem_raw[];
    Smem& s = *reinterpret_cast<Smem*>(smem_raw);
    const int t = threadIdx.x;

    // ---- fold BN into weights (once per block) ----
    if (t < 64) {
        float inv1 = g1[t] * rsqrtf(v1[t] + 1e-5f);
        s.W1[t] = make_float4(W1[3*t+0]*inv1, W1[3*t+1]*inv1, W1[3*t+2]*inv1,
                              be1[t] + (b1[t] - m1[t]) * inv1);
        float inv2 = g2[t] * rsqrtf(v2[t] + 1e-5f);
        s.Inv2[t] = inv2;
        s.C2[t]   = be2[t] + (b2[t] - m2[t]) * inv2;
    }
    if (t < 128) {
        float inv3 = g3[t] * rsqrtf(v3[t] + 1e-5f);
        s.Inv3[t] = inv3;
        s.C3[t]   = be3[t] + (b3[t] - m3[t]) * inv3;
    }
    __syncthreads();
    for (int i = t; i < 64*64; i += THREADS) {
        int o = i >> 6, k = i & 63;
        float w = W2[i] * s.Inv2[o];
        *reinterpret_cast<u64*>(&s.W2D[k][2*o]) = dup2(w);
    }
    for (int i = t; i < 128*64; i += THREADS) {
        int o = i >> 6, k = i & 63;
        float w = W3[i] * s.Inv3[o];
        *reinterpret_cast<u64*>(&s.W3D[k][2*o]) = dup2(w);
    }

    const int cg = t & 15;       // column group (8 cols each)
    const int rg = t >> 4;       // row group
    const int c0 = cg * 8;

    for (int tile = blockIdx.x; tile < NTILES; tile += gridDim.x) {
        const int p0 = tile * TILE;
        __syncthreads();   // protects weight fill (iter 0) and X/Val/Y reuse (iter >0)

        // ---- stage 0: load X tile + valid ----
        for (int i = t; i < 3*TILE; i += THREADS) {
            int ch = i >> 7, p = i & 127;
            s.X[ch][p] = pc[(size_t)ch * NPOS + p0 + p];
        }
        if (t < TILE) s.Val[t] = valid[p0 + t];
        __syncthreads();

        // ---- layer 1: Y1[64][128] = relu(A1 * X + c1) ----
        {
            int p = t & 127, half = t >> 7;
            float x0 = s.X[0][p], x1 = s.X[1][p], x2 = s.X[2][p];
            #pragma unroll
            for (int j = 0; j < 32; ++j) {
                int ch = half * 32 + j;
                float4 w = s.W1[ch];
                float y = fmaf(w.x, x0, fmaf(w.y, x1, fmaf(w.z, x2, w.w)));
                s.Y1[ch][p] = fmaxf(y, 0.f);
            }
        }
        __syncthreads();

        // ---- layer 2: Y2[64][128] = relu(A2 * Y1 + c2) ----
        {
            const int r0 = rg * 4;  // rg in 0..15 -> rows r0..r0+3
            u64 acc[4][4];
            #pragma unroll
            for (int i = 0; i < 4; ++i) {
                u64 d = dup2(s.C2[r0 + i]);
                acc[i][0] = d; acc[i][1] = d; acc[i][2] = d; acc[i][3] = d;
            }
            #pragma unroll 4
            for (int k = 0; k < 64; ++k) {
                const ulonglong2* aw = reinterpret_cast<const ulonglong2*>(&s.W2D[k][2*r0]);
                ulonglong2 A0 = aw[0], A1 = aw[1];
                const ulonglong2* bw = reinterpret_cast<const ulonglong2*>(&s.Y1[k][c0]);
                ulonglong2 B0 = bw[0], B1 = bw[1];
                u64 a[4] = {A0.x, A0.y, A1.x, A1.y};
                u64 b[4] = {B0.x, B0.y, B1.x, B1.y};
                #pragma unroll
                for (int i = 0; i < 4; ++i)
                    #pragma unroll
                    for (int j = 0; j < 4; ++j)
                        acc[i][j] = fma2(a[i], b[j], acc[i][j]);
            }
            #pragma unroll
            for (int i = 0; i < 4; ++i) {
                float r[8];
                #pragma unroll
                for (int j = 0; j < 4; ++j) {
                    F2 q; q.u = acc[i][j];
                    r[2*j+0] = fmaxf(q.f.x, 0.f);
                    r[2*j+1] = fmaxf(q.f.y, 0.f);
                }
                *reinterpret_cast<float4*>(&s.Y2[r0+i][c0])   = make_float4(r[0], r[1], r[2], r[3]);
                *reinterpret_cast<float4*>(&s.Y2[r0+i][c0+4]) = make_float4(r[4], r[5], r[6], r[7]);
            }
        }
        __syncthreads();

        // ---- layer 3: out[128][128] = relu(A3 * Y2 + c3) * valid ----
        {
            const int R0 = rg * 8;  // rows R0..R0+7 of 128
            u64 acc[8][4];
            #pragma unroll
            for (int i = 0; i < 8; ++i) {
                u64 d = dup2(s.C3[R0 + i]);
                acc[i][0] = d; acc[i][1] = d; acc[i][2] = d; acc[i][3] = d;
            }
            #pragma unroll 4
            for (int k = 0; k < 64; ++k) {
                const ulonglong2* aw = reinterpret_cast<const ulonglong2*>(&s.W3D[k][2*R0]);
                ulonglong2 A0 = aw[0], A1 = aw[1], A2 = aw[2], A3 = aw[3];
                const ulonglong2* bw = reinterpret_cast<const ulonglong2*>(&s.Y2[k][c0]);
                ulonglong2 B0 = bw[0], B1 = bw[1];
                u64 a[8] = {A0.x, A0.y, A1.x, A1.y, A2.x, A2.y, A3.x, A3.y};
                u64 b[4] = {B0.x, B0.y, B1.x, B1.y};
                #pragma unroll
                for (int i = 0; i < 8; ++i)
                    #pragma unroll
                    for (int j = 0; j < 4; ++j)
                        acc[i][j] = fma2(a[i], b[j], acc[i][j]);
            }
            // epilogue: relu, mask, store
            float v[8];
            #pragma unroll
            for (int j = 0; j < 8; ++j) v[j] = s.Val[c0 + j];
            #pragma unroll
            for (int i = 0; i < 8; ++i) {
                float r[8];
                #pragma unroll
                for (int j = 0; j < 4; ++j) {
                    F2 q; q.u = acc[i][j];
                    r[2*j+0] = fmaxf(q.f.x, 0.f) * v[2*j+0];
                    r[2*j+1] = fmaxf(q.f.y, 0.f) * v[2*j+1];
                }
                float* dst = out + (size_t)(R0 + i) * NPOS + p0 + c0;
                *reinterpret_cast<float4*>(dst)     = make_float4(r[0], r[1], r[2], r[3]);
                *reinterpret_cast<float4*>(dst + 4) = make_float4(r[4], r[5], r[6], r[7]);
            }
        }
    }
}

extern "C" void kernel_launch(void* const* d_in, const int* in_sizes, int n_in,
                              void* d_out, int out_size)
{
    (void)in_sizes; (void)n_in; (void)out_size;
    cudaFuncSetAttribute(pn_fused_kernel,
                         cudaFuncAttributeMaxDynamicSharedMemorySize,
                         (int)sizeof(Smem));
    pn_fused_kernel<<<NBLOCKS, THREADS, sizeof(Smem)>>>(
        (const float*)d_in[0],  (const float*)d_in[1],
        (const float*)d_in[2],  (const float*)d_in[3],  (const float*)d_in[4],
        (const float*)d_in[5],  (const float*)d_in[6],  (const float*)d_in[7],
        (const float*)d_in[8],  (const float*)d_in[9],  (const float*)d_in[10],
        (const float*)d_in[11], (const float*)d_in[12], (const float*)d_in[13],
        (const float*)d_in[14], (const float*)d_in[15], (const float*)d_in[16],
        (const float*)d_in[17], (const float*)d_in[18], (const float*)d_in[19],
        (float*)d_out);
}